// round 1
// baseline (speedup 1.0000x reference)
#include <cuda_runtime.h>
#include <math.h>

#define N_TOK 16384
#define DMODEL 896
#define INV_SQRT_D 0.03340766f   // 1/sqrt(896)

// ---- scratch (device globals: allocation-free per harness rules) ----
__device__ float g_logit_part[N_TOK * 8];                 // per-(row, colblock) partial dots
__device__ float g_logit[N_TOK];
__device__ float g_ugate[(size_t)N_TOK * DMODEL];

// ---- packed f32x2 helpers (Blackwell FFMA2 path) ----
__device__ __forceinline__ unsigned long long pack_dup(float v) {
    unsigned long long r;
    asm("mov.b64 %0, {%1, %1};" : "=l"(r) : "f"(v));
    return r;
}
__device__ __forceinline__ unsigned long long fma2(unsigned long long a,
                                                   unsigned long long b,
                                                   unsigned long long c) {
    unsigned long long d;
    asm("fma.rn.f32x2 %0, %1, %2, %3;" : "=l"(d) : "l"(a), "l"(b), "l"(c));
    return d;
}
__device__ __forceinline__ float2 unpack2(unsigned long long v) {
    float2 r;
    asm("mov.b64 {%0, %1}, %2;" : "=f"(r.x), "=f"(r.y) : "l"(v));
    return r;
}

// One fused NT-GEMM: C[row, col] = sum_k A[row,k] * W[col,k]  (+ fused epilogue)
// MODE 0: A=u_t (K=896).   Epilogue: partial[row, cb] = sum_col h[row,col]*(C+bias)
// MODE 1: A=[h | alpha*u]  (K=1792). Epilogue: u_gate = sigmoid(C+bias)*alpha*u
// MODE 2: A=[h | u_gate | h*u_gate] (K=2688). Epilogue: out = gelu_erf(C+bias)
template <int MODE>
__global__ void __launch_bounds__(256, 2) fused_gemm(
    const float* __restrict__ hmat,
    const float* __restrict__ umat,
    const float* __restrict__ W,      // [DMODEL, K] row-major
    const float* __restrict__ bias,   // [DMODEL]
    float* __restrict__ dst)          // used in MODE 2 only
{
    constexpr int K = (MODE == 0) ? DMODEL : (MODE == 1 ? 2 * DMODEL : 3 * DMODEL);
    constexpr int NT = K / 16;

    __shared__ __align__(16) float As[16][128];
    __shared__ __align__(16) float Bs[16][128];
    __shared__ float alpha_s[128];

    const int tid = threadIdx.x;
    const int tx = tid & 15;    // 16 col groups of 8
    const int ty = tid >> 4;    // 16 row groups of 8
    const int cb = blockIdx.x;  // 0..6
    const int rb = blockIdx.y;  // 0..127
    const int row0 = rb * 128;
    const int col0 = cb * 128;
    const int lr = tid & 127;   // loader row (A) / loader out-col (B)
    const int q  = tid >> 7;    // loader quad: handles k-quads q and q+2

    if (MODE == 1) {
        if (tid < 128) {
            float lg = g_logit[row0 + tid] * INV_SQRT_D;
            alpha_s[tid] = 1.f / (1.f + expf(-lg));
        }
        __syncthreads();
    }

    auto loadA = [&](int t, int qq) -> float4 {
        const int k0 = t * 16 + qq * 4;
        const size_t rowoff = (size_t)(row0 + lr) * DMODEL;
        if (MODE == 0) {
            return *(const float4*)(umat + rowoff + k0);
        } else if (MODE == 1) {
            if (t < 56) {
                return *(const float4*)(hmat + rowoff + k0);
            } else {
                float4 v = *(const float4*)(umat + rowoff + (k0 - DMODEL));
                const float a = alpha_s[lr];
                v.x *= a; v.y *= a; v.z *= a; v.w *= a;
                return v;
            }
        } else {
            if (t < 56) {
                return *(const float4*)(hmat + rowoff + k0);
            } else if (t < 112) {
                return *(const float4*)(g_ugate + rowoff + (k0 - DMODEL));
            } else {
                const float4 a = *(const float4*)(hmat + rowoff + (k0 - 2 * DMODEL));
                const float4 b = *(const float4*)(g_ugate + rowoff + (k0 - 2 * DMODEL));
                return make_float4(a.x * b.x, a.y * b.y, a.z * b.z, a.w * b.w);
            }
        }
    };
    auto loadB = [&](int t, int qq) -> float4 {
        const int k0 = t * 16 + qq * 4;
        return *(const float4*)(W + (size_t)(col0 + lr) * K + k0);
    };

    unsigned long long acc[4][8];
#pragma unroll
    for (int i = 0; i < 4; i++)
#pragma unroll
        for (int j = 0; j < 8; j++) acc[i][j] = 0ULL;

    float4 pa0 = loadA(0, q), pa1 = loadA(0, q + 2);
    float4 pb0 = loadB(0, q), pb1 = loadB(0, q + 2);

    for (int t = 0; t < NT; t++) {
        // store prefetched tile (transposed to [k][m] / [k][n])
        As[q * 4 + 0][lr] = pa0.x; As[q * 4 + 1][lr] = pa0.y;
        As[q * 4 + 2][lr] = pa0.z; As[q * 4 + 3][lr] = pa0.w;
        As[(q + 2) * 4 + 0][lr] = pa1.x; As[(q + 2) * 4 + 1][lr] = pa1.y;
        As[(q + 2) * 4 + 2][lr] = pa1.z; As[(q + 2) * 4 + 3][lr] = pa1.w;
        Bs[q * 4 + 0][lr] = pb0.x; Bs[q * 4 + 1][lr] = pb0.y;
        Bs[q * 4 + 2][lr] = pb0.z; Bs[q * 4 + 3][lr] = pb0.w;
        Bs[(q + 2) * 4 + 0][lr] = pb1.x; Bs[(q + 2) * 4 + 1][lr] = pb1.y;
        Bs[(q + 2) * 4 + 2][lr] = pb1.z; Bs[(q + 2) * 4 + 3][lr] = pb1.w;
        __syncthreads();

        if (t + 1 < NT) {  // register prefetch overlaps the FMA block below
            pa0 = loadA(t + 1, q); pa1 = loadA(t + 1, q + 2);
            pb0 = loadB(t + 1, q); pb1 = loadB(t + 1, q + 2);
        }

#pragma unroll
        for (int k = 0; k < 16; k++) {
            // a: 8 rows as 4 packed row-pairs (direct 64-bit reads, no repack)
            const longlong2 a01 = *(const longlong2*)&As[k][ty * 8];
            const longlong2 a23 = *(const longlong2*)&As[k][ty * 8 + 4];
            const unsigned long long ap[4] = {
                (unsigned long long)a01.x, (unsigned long long)a01.y,
                (unsigned long long)a23.x, (unsigned long long)a23.y };
            const float4 b0 = *(const float4*)&Bs[k][tx * 8];
            const float4 b1 = *(const float4*)&Bs[k][tx * 8 + 4];
            const unsigned long long bb[8] = {
                pack_dup(b0.x), pack_dup(b0.y), pack_dup(b0.z), pack_dup(b0.w),
                pack_dup(b1.x), pack_dup(b1.y), pack_dup(b1.z), pack_dup(b1.w) };
#pragma unroll
            for (int rp = 0; rp < 4; rp++)
#pragma unroll
                for (int c = 0; c < 8; c++)
                    acc[rp][c] = fma2(ap[rp], bb[c], acc[rp][c]);
        }
        __syncthreads();
    }

    // ---- epilogues ----
    float bc[8];
    {
        const float4 b0 = *(const float4*)(bias + col0 + tx * 8);
        const float4 b1 = *(const float4*)(bias + col0 + tx * 8 + 4);
        bc[0] = b0.x; bc[1] = b0.y; bc[2] = b0.z; bc[3] = b0.w;
        bc[4] = b1.x; bc[5] = b1.y; bc[6] = b1.z; bc[7] = b1.w;
    }

    if (MODE == 0) {
        float rsum[8];
#pragma unroll
        for (int i = 0; i < 8; i++) {
            const int gr = row0 + ty * 8 + i;
            const float4 h0 = *(const float4*)(hmat + (size_t)gr * DMODEL + col0 + tx * 8);
            const float4 h1 = *(const float4*)(hmat + (size_t)gr * DMODEL + col0 + tx * 8 + 4);
            const float hv[8] = {h0.x, h0.y, h0.z, h0.w, h1.x, h1.y, h1.z, h1.w};
            float s = 0.f;
#pragma unroll
            for (int c = 0; c < 8; c++) {
                const float2 v = unpack2(acc[i >> 1][c]);
                const float tval = ((i & 1) ? v.y : v.x) + bc[c];
                s += hv[c] * tval;
            }
            rsum[i] = s;
        }
        // deterministic intra-block reduction over the 16 tx groups (reuse As)
        float* red = &As[0][0];
#pragma unroll
        for (int i = 0; i < 8; i++) red[(ty * 8 + i) * 16 + tx] = rsum[i];
        __syncthreads();
        if (tid < 128) {
            float s = 0.f;
#pragma unroll
            for (int j = 0; j < 16; j++) s += red[tid * 16 + j];
            g_logit_part[(size_t)(row0 + tid) * 8 + cb] = s;
        }
    } else if (MODE == 1) {
#pragma unroll
        for (int i = 0; i < 8; i++) {
            const int gr = row0 + ty * 8 + i;
            const float a = alpha_s[ty * 8 + i];
            const float4 u0 = *(const float4*)(umat + (size_t)gr * DMODEL + col0 + tx * 8);
            const float4 u1 = *(const float4*)(umat + (size_t)gr * DMODEL + col0 + tx * 8 + 4);
            const float uv[8] = {u0.x, u0.y, u0.z, u0.w, u1.x, u1.y, u1.z, u1.w};
            float og[8];
#pragma unroll
            for (int c = 0; c < 8; c++) {
                const float2 v = unpack2(acc[i >> 1][c]);
                const float z = ((i & 1) ? v.y : v.x) + bc[c];
                const float g = 1.f / (1.f + expf(-z));
                og[c] = g * a * uv[c];
            }
            *(float4*)(g_ugate + (size_t)gr * DMODEL + col0 + tx * 8) =
                make_float4(og[0], og[1], og[2], og[3]);
            *(float4*)(g_ugate + (size_t)gr * DMODEL + col0 + tx * 8 + 4) =
                make_float4(og[4], og[5], og[6], og[7]);
        }
    } else {
#pragma unroll
        for (int i = 0; i < 8; i++) {
            const int gr = row0 + ty * 8 + i;
            float og[8];
#pragma unroll
            for (int c = 0; c < 8; c++) {
                const float2 v = unpack2(acc[i >> 1][c]);
                const float z = ((i & 1) ? v.y : v.x) + bc[c];
                og[c] = 0.5f * z * (1.f + erff(z * 0.70710678f));  // exact (erf) GELU
            }
            *(float4*)(dst + (size_t)gr * DMODEL + col0 + tx * 8) =
                make_float4(og[0], og[1], og[2], og[3]);
            *(float4*)(dst + (size_t)gr * DMODEL + col0 + tx * 8 + 4) =
                make_float4(og[4], og[5], og[6], og[7]);
        }
    }
}

__global__ void reduce_logit_kernel() {
    const int i = blockIdx.x * blockDim.x + threadIdx.x;
    if (i < N_TOK) {
        float s = 0.f;
#pragma unroll
        for (int b = 0; b < 7; b++) s += g_logit_part[(size_t)i * 8 + b];
        g_logit[i] = s;
    }
}

extern "C" void kernel_launch(void* const* d_in, const int* in_sizes, int n_in,
                              void* d_out, int out_size) {
    const float* h_t   = (const float*)d_in[0];
    const float* u_t   = (const float*)d_in[1];
    // d_in[2] = token_idx (unused), d_in[3] = u_all (unused)
    const float* W_a_w = (const float*)d_in[4];
    const float* W_a_b = (const float*)d_in[5];
    const float* W_g_w = (const float*)d_in[6];
    const float* W_g_b = (const float*)d_in[7];
    const float* W_f_w = (const float*)d_in[8];
    const float* W_f_b = (const float*)d_in[9];
    float* out = (float*)d_out;

    dim3 grid(DMODEL / 128, N_TOK / 128);  // (7, 128); x-fastest => col-blocks of one row-block co-resident (L2 A-reuse)
    fused_gemm<0><<<grid, 256>>>(h_t, u_t, W_a_w, W_a_b, nullptr);
    reduce_logit_kernel<<<N_TOK / 256, 256>>>();
    fused_gemm<1><<<grid, 256>>>(h_t, u_t, W_g_w, W_g_b, nullptr);
    fused_gemm<2><<<grid, 256>>>(h_t, u_t, W_f_w, W_f_b, out);
}

// round 3
// speedup vs baseline: 2.4334x; 2.4334x over previous
#include <cuda_runtime.h>
#include <cuda_bf16.h>
#include <math.h>
#include <cstdint>

#define N_TOK 16384
#define DMODEL 896
#define KMAX 2688
#define INV_SQRT_D 0.03340766f   // 1/sqrt(896)

// ---------------- scratch (device globals) ----------------
__device__ float g_logit_part[N_TOK * 8];
__device__ float g_logit[N_TOK];
__device__ float g_ugate[(size_t)N_TOK * DMODEL];
__device__ __align__(16) __nv_bfloat16 g_Ahi[(size_t)N_TOK * KMAX];   // 88MB
__device__ __align__(16) __nv_bfloat16 g_Alo[(size_t)N_TOK * KMAX];   // 88MB
__device__ __align__(16) __nv_bfloat16 g_Wahi[DMODEL * DMODEL],     g_Walo[DMODEL * DMODEL];
__device__ __align__(16) __nv_bfloat16 g_Wghi[DMODEL * 2 * DMODEL], g_Wglo[DMODEL * 2 * DMODEL];
__device__ __align__(16) __nv_bfloat16 g_Wfhi[DMODEL * 3 * DMODEL], g_Wflo[DMODEL * 3 * DMODEL];

// ---------------- helpers ----------------
static __device__ __forceinline__ uint32_t smem_u32(const void* p) {
    uint32_t a;
    asm("{ .reg .u64 t; cvta.to.shared.u64 t, %1; cvt.u32.u64 %0, t; }" : "=r"(a) : "l"(p));
    return a;
}
static __device__ __forceinline__ void cp16(uint32_t s, const void* g) {
    asm volatile("cp.async.cg.shared.global [%0], [%1], 16;" :: "r"(s), "l"(g));
}
#define CP_COMMIT() asm volatile("cp.async.commit_group;" ::: "memory")
#define CP_WAIT0()  asm volatile("cp.async.wait_group 0;" ::: "memory")

static __device__ __forceinline__ void ldmx4(uint32_t* r, uint32_t addr) {
    asm volatile("ldmatrix.sync.aligned.m8n8.x4.shared.b16 {%0,%1,%2,%3}, [%4];"
        : "=r"(r[0]), "=r"(r[1]), "=r"(r[2]), "=r"(r[3]) : "r"(addr));
}
static __device__ __forceinline__ void mma16816(float* c, const uint32_t* a,
                                                uint32_t b0, uint32_t b1) {
    asm volatile("mma.sync.aligned.m16n8k16.row.col.f32.bf16.bf16.f32 "
        "{%0,%1,%2,%3}, {%4,%5,%6,%7}, {%8,%9}, {%0,%1,%2,%3};"
        : "+f"(c[0]), "+f"(c[1]), "+f"(c[2]), "+f"(c[3])
        : "r"(a[0]), "r"(a[1]), "r"(a[2]), "r"(a[3]), "r"(b0), "r"(b1));
}

// split a float4 into bf16 hi + residual lo, store 4 elems to each (8B stores)
static __device__ __forceinline__ void split_store(__nv_bfloat16* hi, __nv_bfloat16* lo,
                                                   size_t idx, float4 v) {
    uint32_t h01, h23, l01, l23;
    asm("cvt.rn.bf16x2.f32 %0, %1, %2;" : "=r"(h01) : "f"(v.y), "f"(v.x));
    asm("cvt.rn.bf16x2.f32 %0, %1, %2;" : "=r"(h23) : "f"(v.w), "f"(v.z));
    float hx = __uint_as_float(h01 << 16), hy = __uint_as_float(h01 & 0xffff0000u);
    float hz = __uint_as_float(h23 << 16), hw = __uint_as_float(h23 & 0xffff0000u);
    asm("cvt.rn.bf16x2.f32 %0, %1, %2;" : "=r"(l01) : "f"(v.y - hy), "f"(v.x - hx));
    asm("cvt.rn.bf16x2.f32 %0, %1, %2;" : "=r"(l23) : "f"(v.w - hw), "f"(v.z - hz));
    *(uint2*)(hi + idx) = make_uint2(h01, h23);
    *(uint2*)(lo + idx) = make_uint2(l01, l23);
}

// ---------------- conversion kernels ----------------
__global__ void k_convW(const float* __restrict__ src, __nv_bfloat16* hi,
                        __nv_bfloat16* lo, int n4) {
    int i = blockIdx.x * blockDim.x + threadIdx.x;
    if (i < n4) split_store(hi, lo, (size_t)i * 4, ((const float4*)src)[i]);
}

// src [N,896] f32 -> A[row*KMAX + koff + col] hi/lo ; scaled=1: multiply by alpha(row)
__global__ void k_convA(const float* __restrict__ src, int koff, int scaled) {
    int i = blockIdx.x * blockDim.x + threadIdx.x;
    if (i >= N_TOK * 224) return;
    int row = i / 224, c4 = (i % 224) * 4;
    float4 v = *(const float4*)(src + (size_t)row * DMODEL + c4);
    if (scaled) {
        float a = 1.f / (1.f + __expf(-g_logit[row] * INV_SQRT_D));
        v.x *= a; v.y *= a; v.z *= a; v.w *= a;
    }
    split_store(g_Ahi, g_Alo, (size_t)row * KMAX + koff + c4, v);
}

// g_ugate, h -> A[.,896:1792]=ug ; A[.,1792:2688]=h*ug
__global__ void k_convA2(const float* __restrict__ h) {
    int i = blockIdx.x * blockDim.x + threadIdx.x;
    if (i >= N_TOK * 224) return;
    int row = i / 224, c4 = (i % 224) * 4;
    float4 g = *(const float4*)(g_ugate + (size_t)row * DMODEL + c4);
    float4 hv = *(const float4*)(h + (size_t)row * DMODEL + c4);
    split_store(g_Ahi, g_Alo, (size_t)row * KMAX + DMODEL + c4, g);
    float4 p = make_float4(g.x * hv.x, g.y * hv.y, g.z * hv.z, g.w * hv.w);
    split_store(g_Ahi, g_Alo, (size_t)row * KMAX + 2 * DMODEL + c4, p);
}

__global__ void reduce_logit_kernel() {
    int i = blockIdx.x * blockDim.x + threadIdx.x;
    if (i < N_TOK) {
        float s = 0.f;
#pragma unroll
        for (int b = 0; b < 7; b++) s += g_logit_part[(size_t)i * 8 + b];
        g_logit[i] = s;
    }
}

// ---------------- bf16x3 HMMA GEMM ----------------
// smem stage: Ahi | Alo | Bhi | Blo, each 128 rows x 80B (32 bf16 + 8 pad)
#define ROWB    80
#define TILE_B  (128 * ROWB)     // 10240
#define T_AHI   0
#define T_ALO   TILE_B
#define T_BHI   (2 * TILE_B)
#define T_BLO   (3 * TILE_B)
#define STAGE_B (4 * TILE_B)     // 40960
#define SMEM_BYTES (2 * STAGE_B) // 81920

// MODE 0: K=896 (A at koff 896 = u). Epi: logit partials (needs h, bias)
// MODE 1: K=1792 (A=[h|alpha u]).  Epi: g_ugate = sigmoid(z)*alpha*u
// MODE 2: K=2688 (A=[h|ug|h ug]).  Epi: dst = gelu_erf(z)
template <int MODE>
__global__ void __launch_bounds__(256, 2) hgemm(
    const float* __restrict__ hmat, const float* __restrict__ umat,
    const __nv_bfloat16* __restrict__ Whi, const __nv_bfloat16* __restrict__ Wlo,
    const float* __restrict__ bias, float* __restrict__ dst)
{
    constexpr int K = (MODE == 0) ? 896 : (MODE == 1 ? 1792 : 2688);
    constexpr int AOFF = (MODE == 0) ? 896 : 0;
    constexpr int NT = K / 32;
    extern __shared__ __align__(16) char smem[];
    const uint32_t sb = smem_u32(smem);

    const int tid = threadIdx.x, wid = tid >> 5, l = tid & 31;
    const int cb = blockIdx.x, rb = blockIdx.y;
    const int row0 = rb * 128, col0 = cb * 128;

    // ---- loader mapping: each thread owns one smem row, 2 of 4 16B chunks ----
    const int lrow = tid >> 1, lc = (tid & 1) * 2;
    const __nv_bfloat16* gAh = g_Ahi + (size_t)(row0 + lrow) * KMAX + AOFF + lc * 8;
    const __nv_bfloat16* gAl = g_Alo + (size_t)(row0 + lrow) * KMAX + AOFF + lc * 8;
    const __nv_bfloat16* gBh = Whi + (size_t)(col0 + lrow) * K + lc * 8;
    const __nv_bfloat16* gBl = Wlo + (size_t)(col0 + lrow) * K + lc * 8;
    const uint32_t sl = (uint32_t)(lrow * ROWB + lc * 16);

    auto issue = [&](int t) {
        const uint32_t so = sb + (uint32_t)(t & 1) * STAGE_B + sl;
        const int go = t * 32;
        cp16(so + T_AHI, gAh + go);      cp16(so + T_AHI + 16, gAh + go + 8);
        cp16(so + T_ALO, gAl + go);      cp16(so + T_ALO + 16, gAl + go + 8);
        cp16(so + T_BHI, gBh + go);      cp16(so + T_BHI + 16, gBh + go + 8);
        cp16(so + T_BLO, gBl + go);      cp16(so + T_BLO + 16, gBl + go + 8);
        CP_COMMIT();
    };

    // ---- warp tiling: 2 (M) x 4 (N); warp tile 64x32 ----
    const int wM = wid & 1, wN = wid >> 1;
    const int wMr = wM * 64, wNc = wN * 32;
    const int lq = l >> 2, lr = l & 3;

    float acc[4][4][4];
#pragma unroll
    for (int a = 0; a < 4; a++)
#pragma unroll
        for (int b = 0; b < 4; b++)
#pragma unroll
            for (int c = 0; c < 4; c++) acc[a][b][c] = 0.f;

    const uint32_t aLane = (uint32_t)((wMr + (l & 15)) * ROWB);
    const uint32_t bLane0 = (uint32_t)((wNc + (l & 15)) * ROWB);
    const uint32_t kHalf = (uint32_t)((l >> 4) * 8) * 2;

    issue(0);
    for (int t = 0; t < NT; t++) {
        CP_WAIT0();
        __syncthreads();
        if (t + 1 < NT) issue(t + 1);

        const uint32_t st = sb + (uint32_t)(t & 1) * STAGE_B;
#pragma unroll
        for (int s2 = 0; s2 < 2; s2++) {
            const uint32_t kb = (uint32_t)(s2 * 32) + kHalf;
            uint32_t bh[2][4], bl[2][4];
#pragma unroll
            for (int nj = 0; nj < 2; nj++) {
                ldmx4(bh[nj], st + T_BHI + bLane0 + (uint32_t)(nj * 16 * ROWB) + kb);
                ldmx4(bl[nj], st + T_BLO + bLane0 + (uint32_t)(nj * 16 * ROWB) + kb);
            }
#pragma unroll
            for (int mi = 0; mi < 4; mi++) {
                uint32_t af[4];
                ldmx4(af, st + T_AHI + aLane + (uint32_t)(mi * 16 * ROWB) + kb);
#pragma unroll
                for (int nj = 0; nj < 2; nj++) {
                    mma16816(acc[mi][nj * 2 + 0], af, bh[nj][0], bh[nj][2]);
                    mma16816(acc[mi][nj * 2 + 1], af, bh[nj][1], bh[nj][3]);
                }
#pragma unroll
                for (int nj = 0; nj < 2; nj++) {
                    mma16816(acc[mi][nj * 2 + 0], af, bl[nj][0], bl[nj][2]);
                    mma16816(acc[mi][nj * 2 + 1], af, bl[nj][1], bl[nj][3]);
                }
                ldmx4(af, st + T_ALO + aLane + (uint32_t)(mi * 16 * ROWB) + kb);
#pragma unroll
                for (int nj = 0; nj < 2; nj++) {
                    mma16816(acc[mi][nj * 2 + 0], af, bh[nj][0], bh[nj][2]);
                    mma16816(acc[mi][nj * 2 + 1], af, bh[nj][1], bh[nj][3]);
                }
            }
        }
        __syncthreads();
    }

    // ---- epilogues ----
    // lane (mi, n8): rows wMr+mi*16+lq (+8), cols wNc+n8*8+lr*2 (+1); c-regs [rr*2+cc]
    if (MODE == 0) {
        __syncthreads();  // smem reuse for reduction
        float* red = (float*)smem;  // [128][4]
#pragma unroll
        for (int mi = 0; mi < 4; mi++) {
#pragma unroll
            for (int rr = 0; rr < 2; rr++) {
                const int rloc = wMr + mi * 16 + lq + rr * 8;
                const float* hrow = hmat + (size_t)(row0 + rloc) * DMODEL + col0 + wNc;
                float s = 0.f;
#pragma unroll
                for (int n8 = 0; n8 < 4; n8++) {
                    const int cc = n8 * 8 + lr * 2;
                    float2 h2 = *(const float2*)(hrow + cc);
                    float2 b2 = *(const float2*)(bias + col0 + wNc + cc);
                    s += h2.x * (acc[mi][n8][rr * 2 + 0] + b2.x)
                       + h2.y * (acc[mi][n8][rr * 2 + 1] + b2.y);
                }
                s += __shfl_xor_sync(0xffffffffu, s, 1);
                s += __shfl_xor_sync(0xffffffffu, s, 2);
                if (lr == 0) red[rloc * 4 + wN] = s;
            }
        }
        __syncthreads();
        if (tid < 128) {
            float s = red[tid * 4] + red[tid * 4 + 1] + red[tid * 4 + 2] + red[tid * 4 + 3];
            g_logit_part[(size_t)(row0 + tid) * 8 + cb] = s;
        }
    } else if (MODE == 1) {
#pragma unroll
        for (int mi = 0; mi < 4; mi++) {
#pragma unroll
            for (int rr = 0; rr < 2; rr++) {
                const int rg = row0 + wMr + mi * 16 + lq + rr * 8;
                const float al = 1.f / (1.f + __expf(-g_logit[rg] * INV_SQRT_D));
                const float* urow = umat + (size_t)rg * DMODEL + col0 + wNc;
                float* orow = g_ugate + (size_t)rg * DMODEL + col0 + wNc;
#pragma unroll
                for (int n8 = 0; n8 < 4; n8++) {
                    const int cc = n8 * 8 + lr * 2;
                    float2 b2 = *(const float2*)(bias + col0 + wNc + cc);
                    float2 u2 = *(const float2*)(urow + cc);
                    float z0 = acc[mi][n8][rr * 2 + 0] + b2.x;
                    float z1 = acc[mi][n8][rr * 2 + 1] + b2.y;
                    float2 o;
                    o.x = al * u2.x / (1.f + __expf(-z0));
                    o.y = al * u2.y / (1.f + __expf(-z1));
                    *(float2*)(orow + cc) = o;
                }
            }
        }
    } else {
#pragma unroll
        for (int mi = 0; mi < 4; mi++) {
#pragma unroll
            for (int rr = 0; rr < 2; rr++) {
                const int rg = row0 + wMr + mi * 16 + lq + rr * 8;
                float* orow = dst + (size_t)rg * DMODEL + col0 + wNc;
#pragma unroll
                for (int n8 = 0; n8 < 4; n8++) {
                    const int cc = n8 * 8 + lr * 2;
                    float2 b2 = *(const float2*)(bias + col0 + wNc + cc);
                    float z0 = acc[mi][n8][rr * 2 + 0] + b2.x;
                    float z1 = acc[mi][n8][rr * 2 + 1] + b2.y;
                    float2 o;
                    o.x = 0.5f * z0 * (1.f + erff(z0 * 0.70710678f));
                    o.y = 0.5f * z1 * (1.f + erff(z1 * 0.70710678f));
                    *(float2*)(orow + cc) = o;
                }
            }
        }
    }
}

extern "C" void kernel_launch(void* const* d_in, const int* in_sizes, int n_in,
                              void* d_out, int out_size) {
    const float* h_t   = (const float*)d_in[0];
    const float* u_t   = (const float*)d_in[1];
    const float* W_a_w = (const float*)d_in[4];
    const float* W_a_b = (const float*)d_in[5];
    const float* W_g_w = (const float*)d_in[6];
    const float* W_g_b = (const float*)d_in[7];
    const float* W_f_w = (const float*)d_in[8];
    const float* W_f_b = (const float*)d_in[9];
    float* out = (float*)d_out;

    static bool attr_set = false;
    if (!attr_set) {
        cudaFuncSetAttribute(hgemm<0>, cudaFuncAttributeMaxDynamicSharedMemorySize, SMEM_BYTES);
        cudaFuncSetAttribute(hgemm<1>, cudaFuncAttributeMaxDynamicSharedMemorySize, SMEM_BYTES);
        cudaFuncSetAttribute(hgemm<2>, cudaFuncAttributeMaxDynamicSharedMemorySize, SMEM_BYTES);
        attr_set = true;
    }

    __nv_bfloat16 *Wahi, *Walo, *Wghi, *Wglo, *Wfhi, *Wflo;
    cudaGetSymbolAddress((void**)&Wahi, g_Wahi);
    cudaGetSymbolAddress((void**)&Walo, g_Walo);
    cudaGetSymbolAddress((void**)&Wghi, g_Wghi);
    cudaGetSymbolAddress((void**)&Wglo, g_Wglo);
    cudaGetSymbolAddress((void**)&Wfhi, g_Wfhi);
    cudaGetSymbolAddress((void**)&Wflo, g_Wflo);

    const int nA4 = N_TOK * 224;
    dim3 grid(DMODEL / 128, N_TOK / 128);  // (7, 128)

    k_convW<<<(DMODEL * DMODEL / 4 + 255) / 256, 256>>>(W_a_w, Wahi, Walo, DMODEL * DMODEL / 4);
    k_convW<<<(DMODEL * 2 * DMODEL / 4 + 255) / 256, 256>>>(W_g_w, Wghi, Wglo, DMODEL * 2 * DMODEL / 4);
    k_convW<<<(DMODEL * 3 * DMODEL / 4 + 255) / 256, 256>>>(W_f_w, Wfhi, Wflo, DMODEL * 3 * DMODEL / 4);
    k_convA<<<(nA4 + 255) / 256, 256>>>(h_t, 0, 0);        // h -> [0:896]
    k_convA<<<(nA4 + 255) / 256, 256>>>(u_t, DMODEL, 0);   // u -> [896:1792]

    hgemm<0><<<grid, 256, SMEM_BYTES>>>(h_t, u_t, Wahi, Walo, W_a_b, nullptr);
    reduce_logit_kernel<<<N_TOK / 256, 256>>>();
    k_convA<<<(nA4 + 255) / 256, 256>>>(u_t, DMODEL, 1);   // alpha*u -> [896:1792]
    hgemm<1><<<grid, 256, SMEM_BYTES>>>(h_t, u_t, Wghi, Wglo, W_g_b, nullptr);
    k_convA2<<<(nA4 + 255) / 256, 256>>>(h_t);             // ug, h*ug
    hgemm<2><<<grid, 256, SMEM_BYTES>>>(h_t, u_t, Wfhi, Wflo, W_f_b, out);
}

// round 5
// speedup vs baseline: 2.4432x; 1.0040x over previous
#include <cuda_runtime.h>
#include <cuda_bf16.h>
#include <math.h>
#include <cstdint>

#define N_TOK 16384
#define DMODEL 896
#define KMAX 3584   // [h | alpha*u | ug | h*ug]
#define INV_SQRT_D 0.03340766f   // 1/sqrt(896)

// ---------------- scratch (device globals) ----------------
__device__ float g_logit_part[N_TOK * 8];
__device__ float g_logit[N_TOK];
__device__ __align__(16) __nv_bfloat16 g_Ahi[(size_t)N_TOK * KMAX];   // 117MB
__device__ __align__(16) __nv_bfloat16 g_Alo[(size_t)N_TOK * KMAX];   // 117MB
__device__ __align__(16) __nv_bfloat16 g_Wahi[DMODEL * DMODEL],     g_Walo[DMODEL * DMODEL];
__device__ __align__(16) __nv_bfloat16 g_Wghi[DMODEL * 2 * DMODEL], g_Wglo[DMODEL * 2 * DMODEL];
__device__ __align__(16) __nv_bfloat16 g_Wfhi[DMODEL * 3 * DMODEL], g_Wflo[DMODEL * 3 * DMODEL];

// ---------------- helpers ----------------
static __device__ __forceinline__ uint32_t smem_u32(const void* p) {
    uint32_t a;
    asm("{ .reg .u64 t; cvta.to.shared.u64 t, %1; cvt.u32.u64 %0, t; }" : "=r"(a) : "l"(p));
    return a;
}
static __device__ __forceinline__ void cp16(uint32_t s, const void* g) {
    asm volatile("cp.async.cg.shared.global [%0], [%1], 16;" :: "r"(s), "l"(g));
}
#define CP_COMMIT() asm volatile("cp.async.commit_group;" ::: "memory")
#define CP_WAIT0()  asm volatile("cp.async.wait_group 0;" ::: "memory")

static __device__ __forceinline__ void ldmx4(uint32_t* r, uint32_t addr) {
    asm volatile("ldmatrix.sync.aligned.m8n8.x4.shared.b16 {%0,%1,%2,%3}, [%4];"
        : "=r"(r[0]), "=r"(r[1]), "=r"(r[2]), "=r"(r[3]) : "r"(addr));
}
static __device__ __forceinline__ void mma16816(float* c, const uint32_t* a,
                                                uint32_t b0, uint32_t b1) {
    asm volatile("mma.sync.aligned.m16n8k16.row.col.f32.bf16.bf16.f32 "
        "{%0,%1,%2,%3}, {%4,%5,%6,%7}, {%8,%9}, {%0,%1,%2,%3};"
        : "+f"(c[0]), "+f"(c[1]), "+f"(c[2]), "+f"(c[3])
        : "r"(a[0]), "r"(a[1]), "r"(a[2]), "r"(a[3]), "r"(b0), "r"(b1));
}

// split a float4 into bf16 hi + residual lo, store 4 elems to each (8B stores)
static __device__ __forceinline__ void split_store(__nv_bfloat16* hi, __nv_bfloat16* lo,
                                                   size_t idx, float4 v) {
    uint32_t h01, h23, l01, l23;
    asm("cvt.rn.bf16x2.f32 %0, %1, %2;" : "=r"(h01) : "f"(v.y), "f"(v.x));
    asm("cvt.rn.bf16x2.f32 %0, %1, %2;" : "=r"(h23) : "f"(v.w), "f"(v.z));
    float hx = __uint_as_float(h01 << 16), hy = __uint_as_float(h01 & 0xffff0000u);
    float hz = __uint_as_float(h23 << 16), hw = __uint_as_float(h23 & 0xffff0000u);
    asm("cvt.rn.bf16x2.f32 %0, %1, %2;" : "=r"(l01) : "f"(v.y - hy), "f"(v.x - hx));
    asm("cvt.rn.bf16x2.f32 %0, %1, %2;" : "=r"(l23) : "f"(v.w - hw), "f"(v.z - hz));
    *(uint2*)(hi + idx) = make_uint2(h01, h23);
    *(uint2*)(lo + idx) = make_uint2(l01, l23);
}
// split a float2 (4B stores)
static __device__ __forceinline__ void split_store2(__nv_bfloat16* hi, __nv_bfloat16* lo,
                                                    size_t idx, float2 v) {
    uint32_t h01, l01;
    asm("cvt.rn.bf16x2.f32 %0, %1, %2;" : "=r"(h01) : "f"(v.y), "f"(v.x));
    float hx = __uint_as_float(h01 << 16);
    float hy = __uint_as_float(h01 & 0xffff0000u);
    asm("cvt.rn.bf16x2.f32 %0, %1, %2;" : "=r"(l01) : "f"(v.y - hy), "f"(v.x - hx));
    *(uint32_t*)(hi + idx) = h01;
    *(uint32_t*)(lo + idx) = l01;
}

// ---------------- conversion kernels (fused) ----------------
__global__ void k_convW_all(const float* __restrict__ wa, const float* __restrict__ wg,
                            const float* __restrict__ wf) {
    int i = blockIdx.x * blockDim.x + threadIdx.x;
    const int n1 = DMODEL * DMODEL / 4;
    const int n2 = DMODEL * 2 * DMODEL / 4;
    const int n3 = DMODEL * 3 * DMODEL / 4;
    if (i < n1) {
        split_store(g_Wahi, g_Walo, (size_t)i * 4, ((const float4*)wa)[i]);
    } else if (i < n1 + n2) {
        int j = i - n1;
        split_store(g_Wghi, g_Wglo, (size_t)j * 4, ((const float4*)wg)[j]);
    } else if (i < n1 + n2 + n3) {
        int j = i - n1 - n2;
        split_store(g_Wfhi, g_Wflo, (size_t)j * 4, ((const float4*)wf)[j]);
    }
}

// h -> A[0:896], u -> A[896:1792] (u slot is reused for alpha*u after GEMM1)
__global__ void k_convA_hu(const float* __restrict__ h, const float* __restrict__ u) {
    int i = blockIdx.x * blockDim.x + threadIdx.x;
    const int half = N_TOK * 224;
    if (i < half) {
        int row = i / 224, c4 = (i % 224) * 4;
        split_store(g_Ahi, g_Alo, (size_t)row * KMAX + c4,
                    *(const float4*)(h + (size_t)row * DMODEL + c4));
    } else if (i < 2 * half) {
        int j = i - half;
        int row = j / 224, c4 = (j % 224) * 4;
        split_store(g_Ahi, g_Alo, (size_t)row * KMAX + DMODEL + c4,
                    *(const float4*)(u + (size_t)row * DMODEL + c4));
    }
}

// one warp per row: reduce logit partials, compute alpha, overwrite A[896:1792] with alpha*u
// (runs strictly after hgemm<0>, so no race with its readers)
__global__ void k_alpha(const float* __restrict__ u) {
    const int row = blockIdx.x * 8 + (threadIdx.x >> 5);
    const int l = threadIdx.x & 31;
    float s = (l < 7) ? g_logit_part[(size_t)row * 8 + l] : 0.f;
    s += __shfl_xor_sync(0xffffffffu, s, 1);
    s += __shfl_xor_sync(0xffffffffu, s, 2);
    s += __shfl_xor_sync(0xffffffffu, s, 4);
    s = __shfl_sync(0xffffffffu, s, 0);
    if (l == 0) g_logit[row] = s;
    const float a = 1.f / (1.f + __expf(-s * INV_SQRT_D));
    const float* ur = u + (size_t)row * DMODEL;
    const size_t base = (size_t)row * KMAX + DMODEL;
#pragma unroll
    for (int j = 0; j < 7; j++) {
        const int c4 = (j * 32 + l) * 4;
        float4 v = *(const float4*)(ur + c4);
        v.x *= a; v.y *= a; v.z *= a; v.w *= a;
        split_store(g_Ahi, g_Alo, base + c4, v);
    }
}

// ---------------- bf16x3 HMMA GEMM ----------------
// smem stage: Ahi | Alo | Bhi | Blo, each 128 rows x 80B (32 bf16 + 8 pad)
#define ROWB    80
#define TILE_B  (128 * ROWB)     // 10240
#define T_AHI   0
#define T_ALO   TILE_B
#define T_BHI   (2 * TILE_B)
#define T_BLO   (3 * TILE_B)
#define STAGE_B (4 * TILE_B)     // 40960
#define SMEM_BYTES (2 * STAGE_B) // 81920

// MODE 0: K=896, A = A[896:1792] (u). Epi: logit partials
// MODE 1: K=1792, A = A[0:1792] ([h|alpha u]). Epi: ug -> A[1792:2688], h*ug -> A[2688:3584]
//         (write range disjoint from read range -> no cross-CTA race)
// MODE 2: K=2688, A = {A[0:896), A[1792:3584)} ([h|ug|h*ug]). Epi: dst = gelu_erf(z)
template <int MODE>
__global__ void __launch_bounds__(256, 2) hgemm(
    const float* __restrict__ hmat, const float* __restrict__ umat,
    const __nv_bfloat16* __restrict__ Whi, const __nv_bfloat16* __restrict__ Wlo,
    const float* __restrict__ bias, float* __restrict__ dst)
{
    constexpr int K = (MODE == 0) ? 896 : (MODE == 1 ? 1792 : 2688);
    constexpr int AOFF = (MODE == 0) ? 896 : 0;
    constexpr int NT = K / 32;
    extern __shared__ __align__(16) char smem[];
    const uint32_t sb = smem_u32(smem);

    const int tid = threadIdx.x, wid = tid >> 5, l = tid & 31;
    const int cb = blockIdx.x, rb = blockIdx.y;
    const int row0 = rb * 128, col0 = cb * 128;

    // ---- loader mapping: each thread owns one smem row, 2 of 4 16B chunks ----
    const int lrow = tid >> 1, lc = (tid & 1) * 2;
    const __nv_bfloat16* gAh = g_Ahi + (size_t)(row0 + lrow) * KMAX + AOFF + lc * 8;
    const __nv_bfloat16* gAl = g_Alo + (size_t)(row0 + lrow) * KMAX + AOFF + lc * 8;
    const __nv_bfloat16* gBh = Whi + (size_t)(col0 + lrow) * K + lc * 8;
    const __nv_bfloat16* gBl = Wlo + (size_t)(col0 + lrow) * K + lc * 8;
    const uint32_t sl = (uint32_t)(lrow * ROWB + lc * 16);

    auto issue = [&](int t) {
        const uint32_t so = sb + (uint32_t)(t & 1) * STAGE_B + sl;
        int go = t * 32;
        int ga = go;
        if (MODE == 2 && ga >= DMODEL) ga += DMODEL;  // skip the alpha*u slot
        cp16(so + T_AHI, gAh + ga);      cp16(so + T_AHI + 16, gAh + ga + 8);
        cp16(so + T_ALO, gAl + ga);      cp16(so + T_ALO + 16, gAl + ga + 8);
        cp16(so + T_BHI, gBh + go);      cp16(so + T_BHI + 16, gBh + go + 8);
        cp16(so + T_BLO, gBl + go);      cp16(so + T_BLO + 16, gBl + go + 8);
        CP_COMMIT();
    };

    // ---- warp tiling: 2 (M) x 4 (N); warp tile 64x32 ----
    const int wM = wid & 1, wN = wid >> 1;
    const int wMr = wM * 64, wNc = wN * 32;
    const int lq = l >> 2, lr = l & 3;

    float acc[4][4][4];
#pragma unroll
    for (int a = 0; a < 4; a++)
#pragma unroll
        for (int b = 0; b < 4; b++)
#pragma unroll
            for (int c = 0; c < 4; c++) acc[a][b][c] = 0.f;

    const uint32_t aLane = (uint32_t)((wMr + (l & 15)) * ROWB);
    const uint32_t bLane0 = (uint32_t)((wNc + (l & 15)) * ROWB);
    const uint32_t kHalf = (uint32_t)((l >> 4) * 8) * 2;

    issue(0);
    for (int t = 0; t < NT; t++) {
        CP_WAIT0();
        __syncthreads();
        if (t + 1 < NT) issue(t + 1);

        const uint32_t st = sb + (uint32_t)(t & 1) * STAGE_B;
#pragma unroll
        for (int s2 = 0; s2 < 2; s2++) {
            const uint32_t kb = (uint32_t)(s2 * 32) + kHalf;
            uint32_t bh[2][4], bl[2][4];
#pragma unroll
            for (int nj = 0; nj < 2; nj++) {
                ldmx4(bh[nj], st + T_BHI + bLane0 + (uint32_t)(nj * 16 * ROWB) + kb);
                ldmx4(bl[nj], st + T_BLO + bLane0 + (uint32_t)(nj * 16 * ROWB) + kb);
            }
#pragma unroll
            for (int mi = 0; mi < 4; mi++) {
                uint32_t af[4];
                ldmx4(af, st + T_AHI + aLane + (uint32_t)(mi * 16 * ROWB) + kb);
#pragma unroll
                for (int nj = 0; nj < 2; nj++) {
                    mma16816(acc[mi][nj * 2 + 0], af, bh[nj][0], bh[nj][2]);
                    mma16816(acc[mi][nj * 2 + 1], af, bh[nj][1], bh[nj][3]);
                }
#pragma unroll
                for (int nj = 0; nj < 2; nj++) {
                    mma16816(acc[mi][nj * 2 + 0], af, bl[nj][0], bl[nj][2]);
                    mma16816(acc[mi][nj * 2 + 1], af, bl[nj][1], bl[nj][3]);
                }
                ldmx4(af, st + T_ALO + aLane + (uint32_t)(mi * 16 * ROWB) + kb);
#pragma unroll
                for (int nj = 0; nj < 2; nj++) {
                    mma16816(acc[mi][nj * 2 + 0], af, bh[nj][0], bh[nj][2]);
                    mma16816(acc[mi][nj * 2 + 1], af, bh[nj][1], bh[nj][3]);
                }
            }
        }
        __syncthreads();
    }

    // ---- epilogues ----
    // lane (mi, n8): rows wMr+mi*16+lq (+8), cols wNc+n8*8+lr*2 (+1); c-regs [rr*2+cc]
    if (MODE == 0) {
        __syncthreads();  // smem reuse for reduction
        float* red = (float*)smem;  // [128][4]
#pragma unroll
        for (int mi = 0; mi < 4; mi++) {
#pragma unroll
            for (int rr = 0; rr < 2; rr++) {
                const int rloc = wMr + mi * 16 + lq + rr * 8;
                const float* hrow = hmat + (size_t)(row0 + rloc) * DMODEL + col0 + wNc;
                float s = 0.f;
#pragma unroll
                for (int n8 = 0; n8 < 4; n8++) {
                    const int cc = n8 * 8 + lr * 2;
                    float2 h2 = *(const float2*)(hrow + cc);
                    float2 bb = *(const float2*)(bias + col0 + wNc + cc);
                    s += h2.x * (acc[mi][n8][rr * 2 + 0] + bb.x)
                       + h2.y * (acc[mi][n8][rr * 2 + 1] + bb.y);
                }
                s += __shfl_xor_sync(0xffffffffu, s, 1);
                s += __shfl_xor_sync(0xffffffffu, s, 2);
                if (lr == 0) red[rloc * 4 + wN] = s;
            }
        }
        __syncthreads();
        if (tid < 128) {
            float s = red[tid * 4] + red[tid * 4 + 1] + red[tid * 4 + 2] + red[tid * 4 + 3];
            g_logit_part[(size_t)(row0 + tid) * 8 + cb] = s;
        }
    } else if (MODE == 1) {
#pragma unroll
        for (int mi = 0; mi < 4; mi++) {
#pragma unroll
            for (int rr = 0; rr < 2; rr++) {
                const int rg = row0 + wMr + mi * 16 + lq + rr * 8;
                const float al = 1.f / (1.f + __expf(-g_logit[rg] * INV_SQRT_D));
                const float* urow = umat + (size_t)rg * DMODEL + col0 + wNc;
                const float* hrow = hmat + (size_t)rg * DMODEL + col0 + wNc;
                const size_t base1 = (size_t)rg * KMAX + 2 * DMODEL + col0 + wNc;  // ug
                const size_t base2 = (size_t)rg * KMAX + 3 * DMODEL + col0 + wNc;  // h*ug
#pragma unroll
                for (int n8 = 0; n8 < 4; n8++) {
                    const int cc = n8 * 8 + lr * 2;
                    float2 bb = *(const float2*)(bias + col0 + wNc + cc);
                    float2 u2 = *(const float2*)(urow + cc);
                    float2 h2 = *(const float2*)(hrow + cc);
                    float z0 = acc[mi][n8][rr * 2 + 0] + bb.x;
                    float z1 = acc[mi][n8][rr * 2 + 1] + bb.y;
                    float2 o;
                    o.x = al * u2.x / (1.f + __expf(-z0));
                    o.y = al * u2.y / (1.f + __expf(-z1));
                    split_store2(g_Ahi, g_Alo, base1 + cc, o);
                    split_store2(g_Ahi, g_Alo, base2 + cc,
                                 make_float2(o.x * h2.x, o.y * h2.y));
                }
            }
        }
    } else {
#pragma unroll
        for (int mi = 0; mi < 4; mi++) {
#pragma unroll
            for (int rr = 0; rr < 2; rr++) {
                const int rg = row0 + wMr + mi * 16 + lq + rr * 8;
                float* orow = dst + (size_t)rg * DMODEL + col0 + wNc;
#pragma unroll
                for (int n8 = 0; n8 < 4; n8++) {
                    const int cc = n8 * 8 + lr * 2;
                    float2 bb = *(const float2*)(bias + col0 + wNc + cc);
                    float z0 = acc[mi][n8][rr * 2 + 0] + bb.x;
                    float z1 = acc[mi][n8][rr * 2 + 1] + bb.y;
                    float2 o;
                    o.x = 0.5f * z0 * (1.f + erff(z0 * 0.70710678f));
                    o.y = 0.5f * z1 * (1.f + erff(z1 * 0.70710678f));
                    *(float2*)(orow + cc) = o;
                }
            }
        }
    }
}

extern "C" void kernel_launch(void* const* d_in, const int* in_sizes, int n_in,
                              void* d_out, int out_size) {
    const float* h_t   = (const float*)d_in[0];
    const float* u_t   = (const float*)d_in[1];
    const float* W_a_w = (const float*)d_in[4];
    const float* W_a_b = (const float*)d_in[5];
    const float* W_g_w = (const float*)d_in[6];
    const float* W_g_b = (const float*)d_in[7];
    const float* W_f_w = (const float*)d_in[8];
    const float* W_f_b = (const float*)d_in[9];
    float* out = (float*)d_out;

    cudaFuncSetAttribute(hgemm<0>, cudaFuncAttributeMaxDynamicSharedMemorySize, SMEM_BYTES);
    cudaFuncSetAttribute(hgemm<1>, cudaFuncAttributeMaxDynamicSharedMemorySize, SMEM_BYTES);
    cudaFuncSetAttribute(hgemm<2>, cudaFuncAttributeMaxDynamicSharedMemorySize, SMEM_BYTES);

    __nv_bfloat16 *Wahi, *Walo, *Wghi, *Wglo, *Wfhi, *Wflo;
    cudaGetSymbolAddress((void**)&Wahi, g_Wahi);
    cudaGetSymbolAddress((void**)&Walo, g_Walo);
    cudaGetSymbolAddress((void**)&Wghi, g_Wghi);
    cudaGetSymbolAddress((void**)&Wglo, g_Wglo);
    cudaGetSymbolAddress((void**)&Wfhi, g_Wfhi);
    cudaGetSymbolAddress((void**)&Wflo, g_Wflo);

    dim3 grid(DMODEL / 128, N_TOK / 128);  // (7, 128)
    const int nW = (DMODEL * DMODEL * 6 / 4 + 255) / 256;
    const int nA = (N_TOK * 224 * 2 + 255) / 256;

    // exactly 6 launches; #6 (hgemm<2>) lands in the ncu -s 5 -c 1 window
    k_convW_all<<<nW, 256>>>(W_a_w, W_g_w, W_f_w);                       // 1
    k_convA_hu<<<nA, 256>>>(h_t, u_t);                                   // 2
    hgemm<0><<<grid, 256, SMEM_BYTES>>>(h_t, u_t, Wahi, Walo, W_a_b, nullptr);  // 3
    k_alpha<<<N_TOK / 8, 256>>>(u_t);                                    // 4
    hgemm<1><<<grid, 256, SMEM_BYTES>>>(h_t, u_t, Wghi, Wglo, W_g_b, nullptr);  // 5
    hgemm<2><<<grid, 256, SMEM_BYTES>>>(h_t, u_t, Wfhi, Wflo, W_f_b, out);      // 6
}